// round 9
// baseline (speedup 1.0000x reference)
#include <cuda_runtime.h>
#include <cuda_fp16.h>
#include <cstdint>

#define KC 512
#define DC 256
#define BC 32
#define TC 4096
#define BT 128
#define EPS 2.5e-4f

// ---- smem layout (bytes) ----
#define ZROW 264                 // halfs per z row (256 + 8 pad)
#define ZROWB (ZROW * 2)         // 528 bytes; 528 % 128 == 16 -> conflict-free ldmatrix
#define OFF_Z1 0
#define OFF_Z2 (BT * ZROWB)
#define OFF_WT (2 * BT * ZROWB)
#define WROWB 528
#define WTILE (64 * WROWB)
#define OFF_W2T (OFF_WT + WTILE)
#define OFF_WQ  (OFF_WT + 2 * WTILE)
#define OFF_ZQ  (OFF_WQ + KC * 4)
#define SMEM_BYTES (OFF_ZQ + BT * 4)

// ---- prepped codebook splits (f16, scaled x512) + fp32 norms + ambiguity list ----
__device__ __align__(16) __half g_w1[KC * ZROW];
__device__ __align__(16) __half g_w2[KC * ZROW];
__device__ float g_wq[KC];
__device__ int g_cnt;
__device__ int g_list[BC * TC];

__device__ __forceinline__ uint32_t smem_u32(const void* p) {
    uint32_t a;
    asm("{ .reg .u64 t; cvta.to.shared.u64 t, %1; cvt.u32.u64 %0, t; }" : "=r"(a) : "l"(p));
    return a;
}

__device__ __forceinline__ void ldsm4(uint32_t* r, uint32_t addr) {
    asm volatile("ldmatrix.sync.aligned.m8n8.x4.shared.b16 {%0,%1,%2,%3}, [%4];"
                 : "=r"(r[0]), "=r"(r[1]), "=r"(r[2]), "=r"(r[3]) : "r"(addr));
}

__device__ __forceinline__ void mma16816(float* c, const uint32_t* a, uint32_t b0, uint32_t b1) {
    asm volatile("mma.sync.aligned.m16n8k16.row.col.f32.f16.f16.f32 "
                 "{%0,%1,%2,%3}, {%4,%5,%6,%7}, {%8,%9}, {%0,%1,%2,%3};"
                 : "+f"(c[0]), "+f"(c[1]), "+f"(c[2]), "+f"(c[3])
                 : "r"(a[0]), "r"(a[1]), "r"(a[2]), "r"(a[3]), "r"(b0), "r"(b1));
}

// ---- prep: w' = 512*w split into 2 fp16 parts; R5-style float4-grouped ||w||^2 ----
__global__ void prep_kernel(const float* __restrict__ w) {
    int k = blockIdx.x, d = threadIdx.x;
    if (k == 0 && d == 0) g_cnt = 0;
    float wv = w[k * DC + d];
    float ws = wv * 512.0f;                              // exact pow2 scale
    __half h1 = __float2half_rn(ws);
    __half h2 = __float2half_rn(ws - __half2float(h1));
    g_w1[k * ZROW + d] = h1;
    g_w2[k * ZROW + d] = h2;
    if (d < 8) {
        g_w1[k * ZROW + 256 + d] = __ushort_as_half(0);
        g_w2[k * ZROW + 256 + d] = __ushort_as_half(0);
    }
    if (d == 0) {
        const float4* wr = (const float4*)(w + (size_t)k * DC);
        float s = 0.f;
        #pragma unroll
        for (int c = 0; c < DC / 4; ++c) {
            float4 v = wr[c];
            s += v.x * v.x + v.y * v.y + v.z * v.z + v.w * v.w;
        }
        g_wq[k] = s;
    }
}

// ---- kernel A: fp16x3 split GEMM + rounded-dist top-2 argmin + ambiguity flag ----
__global__ __launch_bounds__(128, 1)
void vq_mma_kernel(const float* __restrict__ z, float* __restrict__ out)
{
    extern __shared__ char smem[];
    const uint32_t sb = smem_u32(smem);
    float*  ztmp = (float*)(smem + OFF_WT);
    __half* z1s  = (__half*)(smem + OFF_Z1);
    __half* z2s  = (__half*)(smem + OFF_Z2);
    float*  wqs  = (float*)(smem + OFF_WQ);
    float*  zqs  = (float*)(smem + OFF_ZQ);

    const int tid = threadIdx.x, lane = tid & 31, wid = tid >> 5;
    const int b = blockIdx.y, t0 = blockIdx.x * BT;
    const float* zb = z + (size_t)b * DC * TC + t0;

    // ---- Prologue: stage fp32 -> exact-serial z_sq -> f16 splits ----
    float zq = 0.f;
    for (int h = 0; h < 2; ++h) {
        if (h) __syncthreads();
        #pragma unroll 4
        for (int i = 0; i < 32; ++i) {
            int f = tid + 128 * i, d = f >> 5, c = f & 31;
            float4 v = *(const float4*)(zb + (size_t)(h * 128 + d) * TC + c * 4);
            *(float4*)(ztmp + d * 132 + c * 4) = v;
        }
        __syncthreads();
        #pragma unroll 8
        for (int d = 0; d < 128; ++d) {
            float v = ztmp[d * 132 + tid];
            zq = __fadd_rn(zq, __fmul_rn(v, v));
        }
        __half2* z1p = (__half2*)(z1s + tid * ZROW + h * 128);
        __half2* z2p = (__half2*)(z2s + tid * ZROW + h * 128);
        #pragma unroll 4
        for (int d = 0; d < 128; d += 2) {
            float a = ztmp[d * 132 + tid], c2v = ztmp[(d + 1) * 132 + tid];
            __half a1 = __float2half_rn(a);
            __half a2 = __float2half_rn(a - __half2float(a1));
            __half b1h = __float2half_rn(c2v);
            __half b2h = __float2half_rn(c2v - __half2float(b1h));
            z1p[d >> 1] = __halves2half2(a1, b1h);
            z2p[d >> 1] = __halves2half2(a2, b2h);
        }
    }
    zqs[tid] = zq;
    #pragma unroll
    for (int i = 0; i < 4; ++i) wqs[tid + 128 * i] = g_wq[tid + 128 * i];
    __syncthreads();

    const uint32_t aOff = (uint32_t)(((lane & 7) + ((lane >> 3) & 1) * 8) * ZROWB + ((lane >> 4) & 1) * 16);
    const uint32_t bOff = (uint32_t)(((lane & 7) + ((lane >> 4) & 1) * 8) * WROWB + ((lane >> 3) & 1) * 16);
    const uint32_t z1b = sb + OFF_Z1 + (uint32_t)wid * 32 * ZROWB + aOff;
    const uint32_t z2b = sb + OFF_Z2 + (uint32_t)wid * 32 * ZROWB + aOff;
    const uint32_t w1b = sb + OFF_WT + bOff;
    const uint32_t w2b = sb + OFF_W2T + bOff;

    float zqr[2][2];
    #pragma unroll
    for (int mt = 0; mt < 2; ++mt)
        #pragma unroll
        for (int hh = 0; hh < 2; ++hh)
            zqr[mt][hh] = zqs[wid * 32 + mt * 16 + hh * 8 + (lane >> 2)];

    unsigned long long b1[2][2], b2[2][2];
    #pragma unroll
    for (int mt = 0; mt < 2; ++mt)
        #pragma unroll
        for (int hh = 0; hh < 2; ++hh) { b1[mt][hh] = ~0ull; b2[mt][hh] = ~0ull; }

    for (int ch = 0; ch < 8; ++ch) {
        {
            const uint4* s1 = (const uint4*)(g_w1 + (size_t)ch * 64 * ZROW);
            const uint4* s2 = (const uint4*)(g_w2 + (size_t)ch * 64 * ZROW);
            uint4* d1 = (uint4*)(smem + OFF_WT);
            uint4* d2 = (uint4*)(smem + OFF_W2T);
            for (int f = tid; f < WTILE / 16; f += 128) { d1[f] = s1[f]; d2[f] = s2[f]; }
        }
        __syncthreads();

        float C[2][8][4];
        #pragma unroll
        for (int mt = 0; mt < 2; ++mt)
            #pragma unroll
            for (int n = 0; n < 8; ++n)
                #pragma unroll
                for (int q = 0; q < 4; ++q) C[mt][n][q] = 0.f;

        #pragma unroll 4
        for (int ks = 0; ks < 16; ++ks) {
            const uint32_t kb = (uint32_t)ks * 32;
            uint32_t A1[2][4], A2[2][4], B1[4][4], B2[4][4];
            ldsm4(A1[0], z1b + kb); ldsm4(A1[1], z1b + 16 * ZROWB + kb);
            ldsm4(A2[0], z2b + kb); ldsm4(A2[1], z2b + 16 * ZROWB + kb);
            #pragma unroll
            for (int p = 0; p < 4; ++p) {
                ldsm4(B1[p], w1b + (uint32_t)p * 16 * WROWB + kb);
                ldsm4(B2[p], w2b + (uint32_t)p * 16 * WROWB + kb);
            }
            #pragma unroll
            for (int mt = 0; mt < 2; ++mt)
                #pragma unroll
                for (int p = 0; p < 4; ++p) {
                    mma16816(C[mt][2 * p],     A1[mt], B1[p][0], B1[p][1]);
                    mma16816(C[mt][2 * p],     A1[mt], B2[p][0], B2[p][1]);
                    mma16816(C[mt][2 * p],     A2[mt], B1[p][0], B1[p][1]);
                    mma16816(C[mt][2 * p + 1], A1[mt], B1[p][2], B1[p][3]);
                    mma16816(C[mt][2 * p + 1], A1[mt], B2[p][2], B2[p][3]);
                    mma16816(C[mt][2 * p + 1], A2[mt], B1[p][2], B1[p][3]);
                }
        }

        // ---- epilogue: exact reference rounding; top-2 packed u64 argmin ----
        #pragma unroll
        for (int mt = 0; mt < 2; ++mt)
            #pragma unroll
            for (int n = 0; n < 8; ++n) {
                int c0 = ch * 64 + n * 8 + 2 * (lane & 3);
                float w0 = wqs[c0], w1v = wqs[c0 + 1];
                #pragma unroll
                for (int hh = 0; hh < 2; ++hh) {
                    float d0 = __fadd_rn(__fsub_rn(zqr[mt][hh], __fmul_rn(C[mt][n][hh * 2 + 0], 0.00390625f)), w0);
                    float d1 = __fadd_rn(__fsub_rn(zqr[mt][hh], __fmul_rn(C[mt][n][hh * 2 + 1], 0.00390625f)), w1v);
                    unsigned long long cA = (((unsigned long long)__float_as_uint(d0)) << 32) | (uint32_t)c0;
                    unsigned long long cB = (((unsigned long long)__float_as_uint(d1)) << 32) | (uint32_t)(c0 + 1);
                    unsigned long long lo = cA < cB ? cA : cB, hi = cA < cB ? cB : cA;
                    if (lo < b1[mt][hh]) { b2[mt][hh] = (b1[mt][hh] < hi) ? b1[mt][hh] : hi; b1[mt][hh] = lo; }
                    else { unsigned long long m = (lo < b2[mt][hh]) ? lo : b2[mt][hh]; b2[mt][hh] = m; }
                }
            }
        __syncthreads();
    }

    // ---- top-2 reduce across the 4 lanes sharing each row; write idx; flag near-ties ----
    #pragma unroll
    for (int mt = 0; mt < 2; ++mt)
        #pragma unroll
        for (int hh = 0; hh < 2; ++hh) {
            unsigned long long v1 = b1[mt][hh], v2 = b2[mt][hh];
            #pragma unroll
            for (int off = 1; off <= 2; off <<= 1) {
                unsigned long long o1 = __shfl_xor_sync(0xffffffffu, v1, off);
                unsigned long long o2 = __shfl_xor_sync(0xffffffffu, v2, off);
                if (o1 < v1) { v2 = (v1 < o2) ? v1 : o2; v1 = o1; }
                else         { v2 = (o1 < v2) ? o1 : v2; }
            }
            if ((lane & 3) == 0) {
                int row = wid * 32 + mt * 16 + hh * 8 + (lane >> 2);
                int qid = b * TC + t0 + row;
                out[qid] = (float)(unsigned int)(v1 & 0xFFFFFFFFull);
                float f1 = __uint_as_float((uint32_t)(v1 >> 32));
                float f2 = __uint_as_float((uint32_t)(v2 >> 32));
                if (__fsub_rn(f2, f1) < EPS) {
                    int idx = atomicAdd(&g_cnt, 1);
                    g_list[idx] = qid;
                }
            }
        }
}

// ---- kernel B: exact R5-semantics re-resolve for flagged queries ----
__global__ __launch_bounds__(256, 1)
void fix_kernel(const float* __restrict__ z, const float* __restrict__ w,
                float* __restrict__ out)
{
    __shared__ float zsh[8][DC];
    const int lane = threadIdx.x & 31, wwid = threadIdx.x >> 5;
    const int wglob = blockIdx.x * 8 + wwid;
    const int nwarp = gridDim.x * 8;
    const int n = g_cnt;

    for (int i = wglob; i < n; i += nwarp) {
        int qid = g_list[i];
        int b = qid >> 12, t = qid & 4095;
        const float* zc = z + (size_t)b * DC * TC + t;
        for (int d = lane; d < DC; d += 32) zsh[wwid][d] = zc[(size_t)d * TC];
        __syncwarp();
        // z_sq: serial d-order, separate mul/add roundings (bit-identical to R5)
        float zq = 0.f;
        for (int d = 0; d < DC; ++d)
            zq = __fadd_rn(zq, __fmul_rn(zsh[wwid][d], zsh[wwid][d]));

        unsigned long long best = ~0ull;
        for (int j0 = 0; j0 < 16; j0 += 4) {
            float acc[4] = {0.f, 0.f, 0.f, 0.f};
            const float* w0 = w + (size_t)(lane + 32 * (j0 + 0)) * DC;
            const float* w1p = w + (size_t)(lane + 32 * (j0 + 1)) * DC;
            const float* w2p = w + (size_t)(lane + 32 * (j0 + 2)) * DC;
            const float* w3p = w + (size_t)(lane + 32 * (j0 + 3)) * DC;
            for (int d = 0; d < DC; ++d) {
                float zv = zsh[wwid][d];
                acc[0] = __fmaf_rn(zv, w0[d], acc[0]);
                acc[1] = __fmaf_rn(zv, w1p[d], acc[1]);
                acc[2] = __fmaf_rn(zv, w2p[d], acc[2]);
                acc[3] = __fmaf_rn(zv, w3p[d], acc[3]);
            }
            #pragma unroll
            for (int u = 0; u < 4; ++u) {
                int k = lane + 32 * (j0 + u);
                float c2 = __fmul_rn(2.0f, acc[u]);
                float t2 = __fsub_rn(zq, c2);
                float s  = __fadd_rn(t2, g_wq[k]);
                unsigned long long cand =
                    (((unsigned long long)__float_as_uint(s)) << 32) | (uint32_t)k;
                if (cand < best) best = cand;
            }
        }
        #pragma unroll
        for (int off = 16; off; off >>= 1) {
            unsigned long long o = __shfl_xor_sync(0xffffffffu, best, off);
            if (o < best) best = o;
        }
        if (lane == 0) out[qid] = (float)(unsigned int)(best & 0xFFFFFFFFull);
        __syncwarp();
    }
}

extern "C" void kernel_launch(void* const* d_in, const int* in_sizes, int n_in,
                              void* d_out, int out_size)
{
    const float* z = (const float*)d_in[0];
    const float* w = (const float*)d_in[1];
    if (n_in >= 2 && in_sizes[0] == KC * DC && in_sizes[1] == BC * DC * TC) {
        z = (const float*)d_in[1];
        w = (const float*)d_in[0];
    }
    float* out = (float*)d_out;
    (void)out_size;

    cudaFuncSetAttribute(vq_mma_kernel,
                         cudaFuncAttributeMaxDynamicSharedMemorySize, SMEM_BYTES);

    prep_kernel<<<KC, DC>>>(w);
    dim3 grid(TC / BT, BC);   // (32, 32)
    vq_mma_kernel<<<grid, 128, SMEM_BYTES>>>(z, out);
    fix_kernel<<<128, 256>>>(z, w, out);
}

// round 10
// speedup vs baseline: 1.0873x; 1.0873x over previous
#include <cuda_runtime.h>
#include <cuda_fp16.h>
#include <cstdint>

#define KC 512
#define DC 256
#define BC 32
#define TC 4096
#define BT 128
#define EPS 2.5e-4f

#define ZROW 264
#define ZROWB 528
#define WROWB 528
#define WTILE (64 * WROWB)            // 33792 B
#define OFF_Z1 0
#define OFF_WT (BT * ZROWB)           // 67584  (ztmp aliases buffer 0 during prologue)
#define OFF_WQ (OFF_WT + 4 * WTILE)   // 202752
#define OFF_ZQ (OFF_WQ + KC * 4)
#define SMEM_BYTES (OFF_ZQ + BT * 4)  // 205312 B

__device__ __align__(16) __half g_w1[KC * ZROW];
__device__ __align__(16) __half g_w2[KC * ZROW];
__device__ float g_wq[KC];
__device__ int g_cnt;
__device__ int g_list[BC * TC];

__device__ __forceinline__ uint32_t smem_u32(const void* p) {
    uint32_t a;
    asm("{ .reg .u64 t; cvta.to.shared.u64 t, %1; cvt.u32.u64 %0, t; }" : "=r"(a) : "l"(p));
    return a;
}
__device__ __forceinline__ void ldsm4(uint32_t* r, uint32_t addr) {
    asm volatile("ldmatrix.sync.aligned.m8n8.x4.shared.b16 {%0,%1,%2,%3}, [%4];"
                 : "=r"(r[0]), "=r"(r[1]), "=r"(r[2]), "=r"(r[3]) : "r"(addr));
}
__device__ __forceinline__ void mma16816(float* c, const uint32_t* a, uint32_t b0, uint32_t b1) {
    asm volatile("mma.sync.aligned.m16n8k16.row.col.f32.f16.f16.f32 "
                 "{%0,%1,%2,%3}, {%4,%5,%6,%7}, {%8,%9}, {%0,%1,%2,%3};"
                 : "+f"(c[0]), "+f"(c[1]), "+f"(c[2]), "+f"(c[3])
                 : "r"(a[0]), "r"(a[1]), "r"(a[2]), "r"(a[3]), "r"(b0), "r"(b1));
}
__device__ __forceinline__ void cp16(uint32_t dst, const void* src) {
    asm volatile("cp.async.cg.shared.global [%0], [%1], 16;" :: "r"(dst), "l"(src));
}

// ---- prep: w' = 512*w split into 2 fp16 parts; fp32 ||w||^2; reset flag count ----
__global__ void prep_kernel(const float* __restrict__ w) {
    int k = blockIdx.x, d = threadIdx.x;
    if (k == 0 && d == 0) g_cnt = 0;
    float wv = w[k * DC + d];
    float ws = wv * 512.0f;
    __half h1 = __float2half_rn(ws);
    __half h2 = __float2half_rn(ws - __half2float(h1));
    g_w1[k * ZROW + d] = h1;
    g_w2[k * ZROW + d] = h2;
    if (d < 8) {
        g_w1[k * ZROW + 256 + d] = __ushort_as_half(0);
        g_w2[k * ZROW + 256 + d] = __ushort_as_half(0);
    }
    if (d == 0) {
        const float4* wr = (const float4*)(w + (size_t)k * DC);
        float s = 0.f;
        #pragma unroll
        for (int c = 0; c < DC / 4; ++c) {
            float4 v = wr[c];
            s += v.x * v.x + v.y * v.y + v.z * v.z + v.w * v.w;
        }
        g_wq[k] = s;
    }
}

// ---- kernel A: z(fp16) x (w1+w2) HMMA + exact-rounded top-2 argmin + EPS flag ----
__global__ __launch_bounds__(256, 1)
void vq_mma_kernel(const float* __restrict__ z, float* __restrict__ out)
{
    extern __shared__ char smem[];
    const uint32_t sb = smem_u32(smem);
    float*  ztmp = (float*)(smem + OFF_WT);    // [128 d][132] fp32, aliases W buf0
    __half* z1s  = (__half*)(smem + OFF_Z1);   // [128 t][264] f16
    float*  wqs  = (float*)(smem + OFF_WQ);
    float*  zqs  = (float*)(smem + OFF_ZQ);

    const int tid = threadIdx.x, lane = tid & 31, wid = tid >> 5;
    const int b = blockIdx.y, t0 = blockIdx.x * BT;
    const float4* zg4 = (const float4*)(z + (size_t)b * DC * TC + t0);

    // ---- Prologue: stage fp32 -> exact-serial z_sq -> f16 convert ----
    float zq = 0.f;
    for (int h = 0; h < 2; ++h) {
        if (h) __syncthreads();
        #pragma unroll 4
        for (int i = 0; i < 16; ++i) {
            int f = tid + 256 * i, d = f >> 5, c = f & 31;
            float4 v = zg4[(size_t)(h * 128 + d) * (TC / 4) + c];
            *(float4*)(ztmp + d * 132 + c * 4) = v;
        }
        __syncthreads();
        if (tid < 128) {
            #pragma unroll 8
            for (int d = 0; d < 128; ++d) {        // serial d-order: validated R5 semantics
                float v = ztmp[d * 132 + tid];
                zq = __fadd_rn(zq, __fmul_rn(v, v));
            }
        }
        {
            int t = tid & 127, db = (tid >> 7) * 64;
            __half2* z1p = (__half2*)(z1s + t * ZROW + h * 128 + db);
            #pragma unroll 4
            for (int dd = 0; dd < 64; dd += 2) {
                float a = ztmp[(db + dd) * 132 + t];
                float c2 = ztmp[(db + dd + 1) * 132 + t];
                z1p[dd >> 1] = __halves2half2(__float2half_rn(a), __float2half_rn(c2));
            }
        }
    }
    if (tid < 128) zqs[tid] = zq;
    #pragma unroll
    for (int i = 0; i < 2; ++i) wqs[tid + 256 * i] = g_wq[tid + 256 * i];
    __syncthreads();                                // converts done; ztmp region free

    // ---- preload W chunk 0 into buffer 0 (cp.async) ----
    {
        const uint4* s1 = (const uint4*)g_w1;
        const uint4* s2 = (const uint4*)g_w2;
        for (int f = tid; f < WTILE / 16; f += 256) {
            cp16(sb + OFF_WT + (uint32_t)f * 16, s1 + f);
            cp16(sb + OFF_WT + WTILE + (uint32_t)f * 16, s2 + f);
        }
        asm volatile("cp.async.commit_group;" ::: "memory");
    }

    const uint32_t aOff = (uint32_t)(((lane & 7) + ((lane >> 3) & 1) * 8) * ZROWB + ((lane >> 4) & 1) * 16);
    const uint32_t bOff = (uint32_t)(((lane & 7) + ((lane >> 4) & 1) * 8) * WROWB + ((lane >> 3) & 1) * 16);
    const uint32_t z1b = sb + OFF_Z1 + (uint32_t)wid * 16 * ZROWB + aOff;

    float zqr[2];
    zqr[0] = zqs[wid * 16 + (lane >> 2)];
    zqr[1] = zqs[wid * 16 + 8 + (lane >> 2)];

    unsigned long long t1[2] = {~0ull, ~0ull}, t2[2] = {~0ull, ~0ull};

    asm volatile("cp.async.wait_group 0;" ::: "memory");
    __syncthreads();

    for (int ch = 0; ch < 8; ++ch) {
        const int cur = ch & 1;
        if (ch < 7) {  // issue next chunk into the other buffer
            const uint4* s1 = (const uint4*)(g_w1 + (size_t)(ch + 1) * 64 * ZROW);
            const uint4* s2 = (const uint4*)(g_w2 + (size_t)(ch + 1) * 64 * ZROW);
            uint32_t dbase = sb + OFF_WT + (uint32_t)(cur ^ 1) * (2 * WTILE);
            for (int f = tid; f < WTILE / 16; f += 256) {
                cp16(dbase + (uint32_t)f * 16, s1 + f);
                cp16(dbase + WTILE + (uint32_t)f * 16, s2 + f);
            }
            asm volatile("cp.async.commit_group;" ::: "memory");
        }

        const uint32_t w1b = sb + OFF_WT + (uint32_t)cur * (2 * WTILE) + bOff;
        const uint32_t w2b = w1b + WTILE;

        float C[8][4];
        #pragma unroll
        for (int n = 0; n < 8; ++n)
            #pragma unroll
            for (int q = 0; q < 4; ++q) C[n][q] = 0.f;

        #pragma unroll 4
        for (int ks = 0; ks < 16; ++ks) {
            const uint32_t kb = (uint32_t)ks * 32;
            uint32_t A[4], B1[4][4], B2[4][4];
            ldsm4(A, z1b + kb);
            #pragma unroll
            for (int p = 0; p < 4; ++p) {
                ldsm4(B1[p], w1b + (uint32_t)p * 16 * WROWB + kb);
                ldsm4(B2[p], w2b + (uint32_t)p * 16 * WROWB + kb);
            }
            // 8 independent MMAs, then 8 dependents at distance 8 (latency hidden)
            #pragma unroll
            for (int p = 0; p < 4; ++p) {
                mma16816(C[2 * p],     A, B1[p][0], B1[p][1]);
                mma16816(C[2 * p + 1], A, B1[p][2], B1[p][3]);
            }
            #pragma unroll
            for (int p = 0; p < 4; ++p) {
                mma16816(C[2 * p],     A, B2[p][0], B2[p][1]);
                mma16816(C[2 * p + 1], A, B2[p][2], B2[p][3]);
            }
        }

        // ---- epilogue: exact reference rounding; top-2 packed u64 argmin ----
        #pragma unroll
        for (int n = 0; n < 8; ++n) {
            int c0 = ch * 64 + n * 8 + 2 * (lane & 3);
            float w0 = wqs[c0], w1v = wqs[c0 + 1];
            #pragma unroll
            for (int hh = 0; hh < 2; ++hh) {
                float d0 = __fadd_rn(__fsub_rn(zqr[hh], __fmul_rn(C[n][hh * 2 + 0], 0.00390625f)), w0);
                float d1 = __fadd_rn(__fsub_rn(zqr[hh], __fmul_rn(C[n][hh * 2 + 1], 0.00390625f)), w1v);
                unsigned long long cA = (((unsigned long long)__float_as_uint(d0)) << 32) | (uint32_t)c0;
                unsigned long long cB = (((unsigned long long)__float_as_uint(d1)) << 32) | (uint32_t)(c0 + 1);
                unsigned long long lo = cA < cB ? cA : cB, hi = cA < cB ? cB : cA;
                if (lo < t1[hh]) { t2[hh] = (t1[hh] < hi) ? t1[hh] : hi; t1[hh] = lo; }
                else { t2[hh] = (lo < t2[hh]) ? lo : t2[hh]; }
            }
        }

        if (ch < 7) {
            asm volatile("cp.async.wait_group 0;" ::: "memory");
            __syncthreads();
        }
    }

    // ---- top-2 reduce across the 4 lanes sharing each row; write + flag ----
    #pragma unroll
    for (int hh = 0; hh < 2; ++hh) {
        unsigned long long v1 = t1[hh], v2 = t2[hh];
        #pragma unroll
        for (int off = 1; off <= 2; off <<= 1) {
            unsigned long long o1 = __shfl_xor_sync(0xffffffffu, v1, off);
            unsigned long long o2 = __shfl_xor_sync(0xffffffffu, v2, off);
            if (o1 < v1) { v2 = (v1 < o2) ? v1 : o2; v1 = o1; }
            else         { v2 = (o1 < v2) ? o1 : v2; }
        }
        if ((lane & 3) == 0) {
            int row = wid * 16 + hh * 8 + (lane >> 2);
            int qid = b * TC + t0 + row;
            out[qid] = (float)(unsigned int)(v1 & 0xFFFFFFFFull);
            float f1 = __uint_as_float((uint32_t)(v1 >> 32));
            float f2 = __uint_as_float((uint32_t)(v2 >> 32));
            if (__fsub_rn(f2, f1) < EPS) {
                int idx = atomicAdd(&g_cnt, 1);
                g_list[idx] = qid;
            }
        }
    }
}

// ---- kernel B: exact R5-semantics re-resolve for flagged queries ----
__global__ __launch_bounds__(256, 1)
void fix_kernel(const float* __restrict__ z, const float* __restrict__ w,
                float* __restrict__ out)
{
    __shared__ float zsh[8][DC];
    const int lane = threadIdx.x & 31, wwid = threadIdx.x >> 5;
    const int wglob = blockIdx.x * 8 + wwid;
    const int nwarp = gridDim.x * 8;
    const int n = g_cnt;

    for (int i = wglob; i < n; i += nwarp) {
        int qid = g_list[i];
        int b = qid >> 12, t = qid & 4095;
        const float* zc = z + (size_t)b * DC * TC + t;
        for (int d = lane; d < DC; d += 32) zsh[wwid][d] = zc[(size_t)d * TC];
        __syncwarp();
        float zq = 0.f;
        for (int d = 0; d < DC; ++d)
            zq = __fadd_rn(zq, __fmul_rn(zsh[wwid][d], zsh[wwid][d]));

        unsigned long long best = ~0ull;
        for (int j0 = 0; j0 < 16; j0 += 4) {
            float acc[4] = {0.f, 0.f, 0.f, 0.f};
            const float* w0 = w + (size_t)(lane + 32 * (j0 + 0)) * DC;
            const float* w1p = w + (size_t)(lane + 32 * (j0 + 1)) * DC;
            const float* w2p = w + (size_t)(lane + 32 * (j0 + 2)) * DC;
            const float* w3p = w + (size_t)(lane + 32 * (j0 + 3)) * DC;
            for (int d = 0; d < DC; ++d) {
                float zv = zsh[wwid][d];
                acc[0] = __fmaf_rn(zv, w0[d], acc[0]);
                acc[1] = __fmaf_rn(zv, w1p[d], acc[1]);
                acc[2] = __fmaf_rn(zv, w2p[d], acc[2]);
                acc[3] = __fmaf_rn(zv, w3p[d], acc[3]);
            }
            #pragma unroll
            for (int u = 0; u < 4; ++u) {
                int k = lane + 32 * (j0 + u);
                float c2 = __fmul_rn(2.0f, acc[u]);
                float t2v = __fsub_rn(zq, c2);
                float s  = __fadd_rn(t2v, g_wq[k]);
                unsigned long long cand =
                    (((unsigned long long)__float_as_uint(s)) << 32) | (uint32_t)k;
                if (cand < best) best = cand;
            }
        }
        #pragma unroll
        for (int off = 16; off; off >>= 1) {
            unsigned long long o = __shfl_xor_sync(0xffffffffu, best, off);
            if (o < best) best = o;
        }
        if (lane == 0) out[qid] = (float)(unsigned int)(best & 0xFFFFFFFFull);
        __syncwarp();
    }
}

extern "C" void kernel_launch(void* const* d_in, const int* in_sizes, int n_in,
                              void* d_out, int out_size)
{
    const float* z = (const float*)d_in[0];
    const float* w = (const float*)d_in[1];
    if (n_in >= 2 && in_sizes[0] == KC * DC && in_sizes[1] == BC * DC * TC) {
        z = (const float*)d_in[1];
        w = (const float*)d_in[0];
    }
    float* out = (float*)d_out;
    (void)out_size;

    cudaFuncSetAttribute(vq_mma_kernel,
                         cudaFuncAttributeMaxDynamicSharedMemorySize, SMEM_BYTES);

    prep_kernel<<<KC, DC>>>(w);
    dim3 grid(TC / BT, BC);   // (32, 32)
    vq_mma_kernel<<<grid, 256, SMEM_BYTES>>>(z, out);
    fix_kernel<<<128, 256>>>(z, w, out);
}